// round 1
// baseline (speedup 1.0000x reference)
#include <cuda_runtime.h>
#include <math_constants.h>

#define BB 16
#define LL 4096
#define HH 8
#define DD 64
#define BH (BB*HH)     // 128
#define UU 45
#define NC 64
#define CLEN 64        // LL/NC

// static scratch (no allocs allowed)
__device__ float g_M[BH*LL];          // sparsity measure
__device__ int   g_Mtop[BH*UU];       // selected query indices (descending M)
__device__ int   g_rank[BH*LL];       // rank of l if selected else -1
__device__ float g_ctx[BH*UU*DD];     // attention outputs for selected rows
__device__ float g_csum[BH*NC*DD];    // per-chunk V sums for the scan

// ---------------- K1: M[bh][l] = max_s(Q_l . K2_s) - sum_s(Q_l . K2_s)/L ----------------
__global__ __launch_bounds__(256) void k1_M(const float* __restrict__ Q,
                                            const float* __restrict__ K,
                                            const int* __restrict__ idxk, int S)
{
    __shared__ float sK2[64*DD];
    int bh = blockIdx.y;
    int b = bh >> 3, h = bh & 7;
    for (int i = threadIdx.x; i < S*DD; i += 256) {
        int s = i >> 6, d = i & 63;
        int kk = idxk[s];
        float v = K[(((size_t)b*LL + kk)*HH + h)*DD + d];
        sK2[i] = v * v;
    }
    __syncthreads();

    int l = blockIdx.x * 256 + threadIdx.x;
    const float4* qp = (const float4*)(Q + (((size_t)b*LL + l)*HH + h)*DD);
    float4 q[16];
    #pragma unroll
    for (int i = 0; i < 16; i++) q[i] = qp[i];

    float mx = -CUDART_INF_F, sm = 0.f;
    for (int s = 0; s < S; s++) {
        const float4* kp = (const float4*)(sK2 + s*DD);
        float dot = 0.f;
        #pragma unroll
        for (int i = 0; i < 16; i++) {
            float4 kv = kp[i];
            dot += q[i].x*kv.x + q[i].y*kv.y + q[i].z*kv.z + q[i].w*kv.w;
        }
        mx = fmaxf(mx, dot);
        sm += dot;
    }
    g_M[bh*LL + l] = mx - sm * (1.0f / (float)LL);
}

// ---------------- K2: per-(b,h) top-45 of M; fills g_Mtop and g_rank ----------------
__global__ __launch_bounds__(256) void k2_topk()
{
    __shared__ float sM[LL];
    __shared__ float rv[8];
    __shared__ int   ri[8];
    int bh = blockIdx.x;
    for (int i = threadIdx.x; i < LL; i += 256) {
        sM[i] = g_M[bh*LL + i];
        g_rank[bh*LL + i] = -1;
    }
    __syncthreads();

    int lane = threadIdx.x & 31, wid = threadIdx.x >> 5;
    for (int it = 0; it < UU; it++) {
        float bv = -CUDART_INF_F; int bi = 0x7fffffff;
        for (int i = threadIdx.x; i < LL; i += 256) {
            float v = sM[i];
            if (v > bv || (v == bv && i < bi)) { bv = v; bi = i; }
        }
        #pragma unroll
        for (int o = 16; o > 0; o >>= 1) {
            float ov = __shfl_down_sync(0xffffffffu, bv, o);
            int   oi = __shfl_down_sync(0xffffffffu, bi, o);
            if (ov > bv || (ov == bv && oi < bi)) { bv = ov; bi = oi; }
        }
        if (lane == 0) { rv[wid] = bv; ri[wid] = bi; }
        __syncthreads();
        if (threadIdx.x == 0) {
            for (int w = 1; w < 8; w++)
                if (rv[w] > bv || (rv[w] == bv && ri[w] < bi)) { bv = rv[w]; bi = ri[w]; }
            g_Mtop[bh*UU + it] = bi;
            g_rank[bh*LL + bi] = it;
            sM[bi] = -CUDART_INF_F;
        }
        __syncthreads();
    }
}

// ---------------- K3: causal-masked softmax attention for the 45 selected rows ----------------
__global__ __launch_bounds__(256) void k3_attn(const float* __restrict__ Kg,
                                               const float* __restrict__ Vg,
                                               const float* __restrict__ Qg)
{
    __shared__ float sc[LL];
    __shared__ float sq[DD];
    __shared__ float red[8];
    __shared__ float bc;
    __shared__ float pacc[4][DD];

    int u = blockIdx.x, bh = blockIdx.y;
    int b = bh >> 3, h = bh & 7;
    int qidx = g_Mtop[bh*UU + u];
    if (threadIdx.x < 16)
        ((float4*)sq)[threadIdx.x] =
            ((const float4*)(Qg + (((size_t)b*LL + qidx)*HH + h)*DD))[threadIdx.x];
    __syncthreads();

    float4 q[16];
    #pragma unroll
    for (int i = 0; i < 16; i++) q[i] = ((float4*)sq)[i];

    const float scale = 0.125f;  // 1/sqrt(64)
    int kmax = qidx;             // causal: keys <= qidx (inclusive)

    float lmax = -CUDART_INF_F;
    for (int k = threadIdx.x; k <= kmax; k += 256) {
        const float4* kp = (const float4*)(Kg + (((size_t)b*LL + k)*HH + h)*DD);
        float dot = 0.f;
        #pragma unroll
        for (int i = 0; i < 16; i++) {
            float4 kv = kp[i];
            dot += q[i].x*kv.x + q[i].y*kv.y + q[i].z*kv.z + q[i].w*kv.w;
        }
        dot *= scale;
        sc[k] = dot;
        lmax = fmaxf(lmax, dot);
    }

    int lane = threadIdx.x & 31, wid = threadIdx.x >> 5;
    #pragma unroll
    for (int o = 16; o > 0; o >>= 1) lmax = fmaxf(lmax, __shfl_xor_sync(0xffffffffu, lmax, o));
    if (lane == 0) red[wid] = lmax;
    __syncthreads();
    if (threadIdx.x == 0) {
        float m = red[0];
        for (int w = 1; w < 8; w++) m = fmaxf(m, red[w]);
        bc = m;
    }
    __syncthreads();
    float gmax = bc;

    float lsum = 0.f;
    for (int k = threadIdx.x; k <= kmax; k += 256) {
        float w = __expf(sc[k] - gmax);
        sc[k] = w;
        lsum += w;
    }
    #pragma unroll
    for (int o = 16; o > 0; o >>= 1) lsum += __shfl_xor_sync(0xffffffffu, lsum, o);
    if (lane == 0) red[wid] = lsum;
    __syncthreads();
    if (threadIdx.x == 0) {
        float ssum = 0.f;
        for (int w = 0; w < 8; w++) ssum += red[w];
        bc = ssum;
    }
    __syncthreads();
    float gsum = bc;

    int r = threadIdx.x >> 6, d = threadIdx.x & 63;
    float acc = 0.f;
    for (int k = r; k <= kmax; k += 4)
        acc += sc[k] * Vg[(((size_t)b*LL + k)*HH + h)*DD + d];
    pacc[r][d] = acc;
    __syncthreads();
    if (threadIdx.x < DD) {
        int dd = threadIdx.x;
        float o = (pacc[0][dd] + pacc[1][dd] + pacc[2][dd] + pacc[3][dd]) / gsum;
        g_ctx[(bh*UU + u)*DD + dd] = o;
    }
}

// ---------------- K4: per-chunk V sums (pass 1 of the cumsum) ----------------
__global__ __launch_bounds__(256) void k4_csum(const float* __restrict__ Vg)
{
    __shared__ float p[4][DD];
    int c = blockIdx.x, bh = blockIdx.y, b = bh >> 3, h = bh & 7;
    int r = threadIdx.x >> 6, d = threadIdx.x & 63;
    float acc = 0.f;
    int l0 = c * CLEN;
    for (int j = r; j < CLEN; j += 4)
        acc += Vg[(((size_t)b*LL + l0 + j)*HH + h)*DD + d];
    p[r][d] = acc;
    __syncthreads();
    if (threadIdx.x < DD) {
        int dd = threadIdx.x;
        g_csum[(bh*NC + c)*DD + dd] = p[0][dd] + p[1][dd] + p[2][dd] + p[3][dd];
    }
}

// ---------------- K5: local scan + prefix offset + scatter of attention rows ----------------
__global__ __launch_bounds__(256) void k5_scan(const float* __restrict__ Vg,
                                               float* __restrict__ out)
{
    int bh = blockIdx.y, b = bh >> 3, h = bh & 7;
    int g = threadIdx.x >> 6, d = threadIdx.x & 63;
    int c = blockIdx.x * 4 + g;

    float acc = 0.f;
    for (int cc = 0; cc < c; cc++)
        acc += g_csum[(bh*NC + cc)*DD + d];

    int base = c * CLEN;
    for (int j = 0; j < CLEN; j += 4) {
        float v[4]; int rr[4];
        #pragma unroll
        for (int t = 0; t < 4; t++) {
            int l = base + j + t;
            v[t]  = Vg[(((size_t)b*LL + l)*HH + h)*DD + d];
            rr[t] = g_rank[bh*LL + l];
        }
        #pragma unroll
        for (int t = 0; t < 4; t++) {
            acc += v[t];
            float o = acc;
            if (rr[t] >= 0) o = g_ctx[(bh*UU + rr[t])*DD + d];
            out[(((size_t)b*LL + base + j + t)*HH + h)*DD + d] = o;
        }
    }
}

extern "C" void kernel_launch(void* const* d_in, const int* in_sizes, int n_in,
                              void* d_out, int out_size)
{
    const float* Q    = (const float*)d_in[0];
    const float* K    = (const float*)d_in[1];
    const float* V    = (const float*)d_in[2];
    const int*   idxk = (const int*)d_in[3];
    int S = in_sizes[3];
    float* out = (float*)d_out;

    k1_M   <<<dim3(LL/256, BH), 256>>>(Q, K, idxk, S);
    k2_topk<<<BH, 256>>>();
    k3_attn<<<dim3(UU, BH), 256>>>(K, V, Q);
    k4_csum<<<dim3(NC, BH), 256>>>(V);
    k5_scan<<<dim3(NC/4, BH), 256>>>(V, out);
}

// round 2
// speedup vs baseline: 1.2888x; 1.2888x over previous
#include <cuda_runtime.h>
#include <math_constants.h>

#define BB 16
#define LL 4096
#define HH 8
#define DD 64
#define BH (BB*HH)     // 128
#define UU 45
#define NC 64
#define CLEN 64        // LL/NC

#define TQ 48          // queries padded (45 real + 3 dummy)
#define TK 64          // key tile
#define SP 68          // padded smem row stride in floats (272B, 16B aligned)

typedef unsigned long long u64;

__device__ __forceinline__ void fma2(u64 &d, u64 a, u64 b){
    asm("fma.rn.f32x2 %0, %1, %2, %0;" : "+l"(d) : "l"(a), "l"(b));
}
__device__ __forceinline__ u64 pack2(float x, float y){
    u64 r; asm("mov.b64 %0, {%1, %2};" : "=l"(r) : "f"(x), "f"(y)); return r;
}
__device__ __forceinline__ float2 unpack2(u64 v){
    float2 r; asm("mov.b64 {%0, %1}, %2;" : "=f"(r.x), "=f"(r.y) : "l"(v)); return r;
}
__device__ __forceinline__ void mul2(u64 &d, u64 a, u64 b){
    asm("mul.rn.f32x2 %0, %1, %2;" : "=l"(d) : "l"(a), "l"(b));
}

// static scratch (no allocs allowed)
__device__ float g_M[BH*LL];
__device__ int   g_Mtop[BH*UU];
__device__ int   g_rank[BH*LL];
__device__ float g_ctx[BH*UU*DD];
__device__ float g_csum[BH*NC*DD];

// ---------------- K1: M[bh][l] = max_s(Q_l . K2_s) - sum_s(Q_l . K2_s)/L ----------------
__global__ __launch_bounds__(256) void k1_M(const float* __restrict__ Q,
                                            const float* __restrict__ K,
                                            const int* __restrict__ idxk, int S)
{
    __shared__ __align__(16) float sK2[UU*DD];
    int bh = blockIdx.y;
    int b = bh >> 3, h = bh & 7;
    for (int i = threadIdx.x; i < S*DD; i += 256) {
        int s = i >> 6, d = i & 63;
        int kk = idxk[s];
        float v = K[(((size_t)b*LL + kk)*HH + h)*DD + d];
        sK2[i] = v * v;
    }
    __syncthreads();

    int l = blockIdx.x * 256 + threadIdx.x;
    const ulonglong2* qp = (const ulonglong2*)(Q + (((size_t)b*LL + l)*HH + h)*DD);
    u64 q[32];
    #pragma unroll
    for (int i = 0; i < 16; i++) { ulonglong2 t = qp[i]; q[2*i] = t.x; q[2*i+1] = t.y; }

    float mx = -CUDART_INF_F, sm = 0.f;
    for (int s = 0; s < S; s++) {
        const ulonglong2* kp = (const ulonglong2*)(sK2 + s*DD);
        u64 acc[4] = {0ull, 0ull, 0ull, 0ull};
        #pragma unroll
        for (int i = 0; i < 16; i++) {
            ulonglong2 kv = kp[i];
            fma2(acc[(2*i) & 3], q[2*i],   kv.x);
            fma2(acc[(2*i+1) & 3], q[2*i+1], kv.y);
        }
        float2 f0 = unpack2(acc[0]), f1 = unpack2(acc[1]);
        float2 f2 = unpack2(acc[2]), f3 = unpack2(acc[3]);
        float dot = ((f0.x + f1.x) + (f2.x + f3.x)) + ((f0.y + f1.y) + (f2.y + f3.y));
        mx = fmaxf(mx, dot);
        sm += dot;
    }
    g_M[bh*LL + l] = mx - sm * (1.0f / (float)LL);
}

// ---------------- K2: per-(b,h) top-45 of M ----------------
__global__ __launch_bounds__(256) void k2_topk()
{
    __shared__ float sM[LL];
    __shared__ float rv[8];
    __shared__ int   ri[8];
    int bh = blockIdx.x;
    for (int i = threadIdx.x; i < LL; i += 256) {
        sM[i] = g_M[bh*LL + i];
        g_rank[bh*LL + i] = -1;
    }
    __syncthreads();

    int lane = threadIdx.x & 31, wid = threadIdx.x >> 5;
    for (int it = 0; it < UU; it++) {
        float bv = -CUDART_INF_F; int bi = 0x7fffffff;
        for (int i = threadIdx.x; i < LL; i += 256) {
            float v = sM[i];
            if (v > bv || (v == bv && i < bi)) { bv = v; bi = i; }
        }
        #pragma unroll
        for (int o = 16; o > 0; o >>= 1) {
            float ov = __shfl_down_sync(0xffffffffu, bv, o);
            int   oi = __shfl_down_sync(0xffffffffu, bi, o);
            if (ov > bv || (ov == bv && oi < bi)) { bv = ov; bi = oi; }
        }
        if (lane == 0) { rv[wid] = bv; ri[wid] = bi; }
        __syncthreads();
        if (threadIdx.x == 0) {
            for (int w = 1; w < 8; w++)
                if (rv[w] > bv || (rv[w] == bv && ri[w] < bi)) { bv = rv[w]; bi = ri[w]; }
            g_Mtop[bh*UU + it] = bi;
            g_rank[bh*LL + bi] = it;
            sM[bi] = -CUDART_INF_F;
        }
        __syncthreads();
    }
}

// ---------------- K3: flash-style attention for the 45 selected rows, 1 block per (b,h) ----------------
__global__ __launch_bounds__(256) void k3_attn(const float* __restrict__ Kg,
                                               const float* __restrict__ Vg,
                                               const float* __restrict__ Qg)
{
    __shared__ __align__(16) float sQ[TQ*SP];
    __shared__ __align__(16) float sKV[TK*SP];
    __shared__ __align__(16) float sS[TQ*SP];
    __shared__ float s_m[TQ], s_l[TQ], s_c[TQ];
    __shared__ int   s_qi[TQ];
    __shared__ int   s_maxq;

    int bh = blockIdx.x;
    int b = bh >> 3, h = bh & 7;
    int tid = threadIdx.x;

    if (tid < TQ) {
        int qi = (tid < UU) ? g_Mtop[bh*UU + tid] : -1;
        s_qi[tid] = qi;
        s_m[tid] = -CUDART_INF_F;
        s_l[tid] = 0.f;
    }
    __syncthreads();
    if (tid == 0) {
        int m = -1;
        for (int i = 0; i < TQ; i++) m = max(m, s_qi[i]);
        s_maxq = m;
    }
    // load Q rows (48 rows x 16 float4)
    for (int i = tid; i < TQ*16; i += 256) {
        int q = i >> 4, dv = i & 15;
        int row = s_qi[q];
        float4 v = make_float4(0.f, 0.f, 0.f, 0.f);
        if (row >= 0)
            v = ((const float4*)(Qg + (((size_t)b*LL + row)*HH + h)*DD))[dv];
        ((float4*)(sQ + q*SP))[dv] = v;
    }
    __syncthreads();

    int qg = tid >> 4, lg = tid & 15;  // lg: key-group (QK) or dim-group (PV)
    int q0 = qg*3, k0 = lg*4, d0g = lg;

    u64 o0[3], o1[3];                   // O accum: 3q x 4d as 2 packed each
    #pragma unroll
    for (int j = 0; j < 3; j++) { o0[j] = 0ull; o1[j] = 0ull; }

    const float scale = 0.125f;

    for (int t0 = 0; t0 < LL; t0 += TK) {
        if (t0 > s_maxq) break;

        // ---- load K tile ----
        for (int i = tid; i < TK*16; i += 256) {
            int r = i >> 4, dv = i & 15;
            ((float4*)(sKV + r*SP))[dv] =
                ((const float4*)(Kg + (((size_t)b*LL + t0 + r)*HH + h)*DD))[dv];
        }
        __syncthreads();

        // ---- QK: scores S[48][64], micro-tile 3q x 4k per thread ----
        {
            u64 aA[3][4], aB[3][4];
            #pragma unroll
            for (int j = 0; j < 3; j++)
                #pragma unroll
                for (int t = 0; t < 4; t++) { aA[j][t] = 0ull; aB[j][t] = 0ull; }
            #pragma unroll
            for (int dv = 0; dv < 16; dv++) {
                ulonglong2 qv[3];
                #pragma unroll
                for (int j = 0; j < 3; j++)
                    qv[j] = ((const ulonglong2*)(sQ + (q0+j)*SP))[dv];
                ulonglong2 kv[4];
                #pragma unroll
                for (int t = 0; t < 4; t++)
                    kv[t] = ((const ulonglong2*)(sKV + (k0+t)*SP))[dv];
                #pragma unroll
                for (int j = 0; j < 3; j++)
                    #pragma unroll
                    for (int t = 0; t < 4; t++) {
                        fma2(aA[j][t], qv[j].x, kv[t].x);
                        fma2(aB[j][t], qv[j].y, kv[t].y);
                    }
            }
            #pragma unroll
            for (int j = 0; j < 3; j++)
                #pragma unroll
                for (int t = 0; t < 4; t++) {
                    float2 fa = unpack2(aA[j][t]);
                    float2 fb = unpack2(aB[j][t]);
                    sS[(q0+j)*SP + k0 + t] = ((fa.x + fa.y) + (fb.x + fb.y)) * scale;
                }
        }
        __syncthreads();

        // ---- load V tile into sKV (K no longer needed) + stats pass 1 ----
        for (int i = tid; i < TK*16; i += 256) {
            int r = i >> 4, dv = i & 15;
            ((float4*)(sKV + r*SP))[dv] =
                ((const float4*)(Vg + (((size_t)b*LL + t0 + r)*HH + h)*DD))[dv];
        }
        if (tid < TQ) {
            int qi = s_qi[tid];
            int vlim = qi - t0;
            float tm = -CUDART_INF_F;
            if (vlim >= 0) {
                int n = min(vlim + 1, TK);
                for (int k = 0; k < n; k++) tm = fmaxf(tm, sS[tid*SP + k]);
            }
            float m_old = s_m[tid];
            float m_new = fmaxf(m_old, tm);
            float c = (m_new == -CUDART_INF_F) ? 1.f : __expf(m_old - m_new);
            s_c[tid] = c;
            s_m[tid] = m_new;
        }
        __syncthreads();

        // ---- exp pass: P = exp(S - m), causal masked ----
        #pragma unroll
        for (int j = 0; j < 3; j++) {
            int q = q0 + j;
            int qi = s_qi[q];
            float mq = s_m[q];
            #pragma unroll
            for (int t = 0; t < 4; t++) {
                int k = k0 + t;
                float sval = sS[q*SP + k];
                float p = 0.f;
                if ((t0 + k) <= qi && mq != -CUDART_INF_F) p = __expf(sval - mq);
                sS[q*SP + k] = p;
            }
        }
        __syncthreads();

        // ---- l update ----
        if (tid < TQ) {
            float sum = 0.f;
            for (int k = 0; k < TK; k++) sum += sS[tid*SP + k];
            s_l[tid] = s_l[tid]*s_c[tid] + sum;
        }
        __syncthreads();

        // ---- rescale O + PV accumulate ----
        #pragma unroll
        for (int j = 0; j < 3; j++) {
            float c = s_c[q0 + j];
            u64 cp = pack2(c, c);
            mul2(o0[j], o0[j], cp);
            mul2(o1[j], o1[j], cp);
        }
        for (int kb = 0; kb < TK; kb += 4) {
            float4 sv[3];
            #pragma unroll
            for (int j = 0; j < 3; j++)
                sv[j] = *(const float4*)(sS + (q0+j)*SP + kb);
            ulonglong2 vv[4];
            #pragma unroll
            for (int t = 0; t < 4; t++)
                vv[t] = ((const ulonglong2*)(sKV + (kb+t)*SP))[d0g];
            #pragma unroll
            for (int j = 0; j < 3; j++) {
                float sj[4] = {sv[j].x, sv[j].y, sv[j].z, sv[j].w};
                #pragma unroll
                for (int t = 0; t < 4; t++) {
                    u64 sp = pack2(sj[t], sj[t]);
                    fma2(o0[j], sp, vv[t].x);
                    fma2(o1[j], sp, vv[t].y);
                }
            }
        }
        __syncthreads();
    }

    // ---- epilogue: O /= l, write g_ctx ----
    #pragma unroll
    for (int j = 0; j < 3; j++) {
        int q = q0 + j;
        if (q < UU) {
            float inv = 1.f / s_l[q];
            float2 a = unpack2(o0[j]);
            float2 c = unpack2(o1[j]);
            float* dst = g_ctx + (bh*UU + q)*DD + d0g*4;
            dst[0] = a.x*inv; dst[1] = a.y*inv;
            dst[2] = c.x*inv; dst[3] = c.y*inv;
        }
    }
}

// ---------------- K4: per-chunk V sums (pass 1 of the cumsum) ----------------
__global__ __launch_bounds__(256) void k4_csum(const float* __restrict__ Vg)
{
    __shared__ float p[4][DD];
    int c = blockIdx.x, bh = blockIdx.y, b = bh >> 3, h = bh & 7;
    int r = threadIdx.x >> 6, d = threadIdx.x & 63;
    float acc = 0.f;
    int l0 = c * CLEN;
    for (int j = r; j < CLEN; j += 4)
        acc += Vg[(((size_t)b*LL + l0 + j)*HH + h)*DD + d];
    p[r][d] = acc;
    __syncthreads();
    if (threadIdx.x < DD) {
        int dd = threadIdx.x;
        g_csum[(bh*NC + c)*DD + dd] = p[0][dd] + p[1][dd] + p[2][dd] + p[3][dd];
    }
}

// ---------------- K5: local scan + prefix offset + scatter of attention rows ----------------
__global__ __launch_bounds__(256) void k5_scan(const float* __restrict__ Vg,
                                               float* __restrict__ out)
{
    int bh = blockIdx.y, b = bh >> 3, h = bh & 7;
    int g = threadIdx.x >> 6, d = threadIdx.x & 63;
    int c = blockIdx.x * 4 + g;

    float acc = 0.f;
    for (int cc = 0; cc < c; cc++)
        acc += g_csum[(bh*NC + cc)*DD + d];

    int base = c * CLEN;
    for (int j = 0; j < CLEN; j += 4) {
        float v[4]; int rr[4];
        #pragma unroll
        for (int t = 0; t < 4; t++) {
            int l = base + j + t;
            v[t]  = Vg[(((size_t)b*LL + l)*HH + h)*DD + d];
            rr[t] = g_rank[bh*LL + l];
        }
        #pragma unroll
        for (int t = 0; t < 4; t++) {
            acc += v[t];
            float o = acc;
            if (rr[t] >= 0) o = g_ctx[(bh*UU + rr[t])*DD + d];
            out[(((size_t)b*LL + base + j + t)*HH + h)*DD + d] = o;
        }
    }
}

extern "C" void kernel_launch(void* const* d_in, const int* in_sizes, int n_in,
                              void* d_out, int out_size)
{
    const float* Q    = (const float*)d_in[0];
    const float* K    = (const float*)d_in[1];
    const float* V    = (const float*)d_in[2];
    const int*   idxk = (const int*)d_in[3];
    int S = in_sizes[3];
    float* out = (float*)d_out;

    k1_M   <<<dim3(LL/256, BH), 256>>>(Q, K, idxk, S);
    k2_topk<<<BH, 256>>>();
    k3_attn<<<BH, 256>>>(K, V, Q);
    k4_csum<<<dim3(NC, BH), 256>>>(V);
    k5_scan<<<dim3(NC/4, BH), 256>>>(V, out);
}

// round 3
// speedup vs baseline: 1.5099x; 1.1715x over previous
#include <cuda_runtime.h>
#include <math_constants.h>

#define BB 16
#define LL 4096
#define HH 8
#define DD 64
#define BH (BB*HH)     // 128
#define UU 45
#define NC 64
#define CLEN 64        // LL/NC

#define TQ 48          // queries padded (45 real + 3 dummy)
#define TK 64          // key tile
#define SP 68          // padded smem row stride in floats

typedef unsigned long long u64;

__device__ __forceinline__ void fma2(u64 &d, u64 a, u64 b){
    asm("fma.rn.f32x2 %0, %1, %2, %0;" : "+l"(d) : "l"(a), "l"(b));
}
__device__ __forceinline__ u64 pack2(float x, float y){
    u64 r; asm("mov.b64 %0, {%1, %2};" : "=l"(r) : "f"(x), "f"(y)); return r;
}
__device__ __forceinline__ float2 unpack2(u64 v){
    float2 r; asm("mov.b64 {%0, %1}, %2;" : "=f"(r.x), "=f"(r.y) : "l"(v)); return r;
}
__device__ __forceinline__ void mul2(u64 &d, u64 a, u64 b){
    asm("mul.rn.f32x2 %0, %1, %2;" : "=l"(d) : "l"(a), "l"(b));
}

// static scratch (no allocs allowed)
__device__ float g_M[BH*LL];
__device__ int   g_Mtop[BH*UU];
__device__ int   g_rank[BH*LL];
__device__ float g_ctx[BH*UU*DD];
__device__ float g_csum[BH*NC*DD];

// ---------------- K1: M[bh][l] = max_s(Q_l . K2_s) - sum_s(Q_l . K2_s)/L ----------------
__global__ __launch_bounds__(256) void k1_M(const float* __restrict__ Q,
                                            const float* __restrict__ K,
                                            const int* __restrict__ idxk, int S)
{
    __shared__ __align__(16) float sK2[UU*DD];
    int bh = blockIdx.y;
    int b = bh >> 3, h = bh & 7;
    for (int i = threadIdx.x; i < S*DD; i += 256) {
        int s = i >> 6, d = i & 63;
        int kk = idxk[s];
        float v = K[(((size_t)b*LL + kk)*HH + h)*DD + d];
        sK2[i] = v * v;
    }
    __syncthreads();

    int l = blockIdx.x * 256 + threadIdx.x;
    const ulonglong2* qp = (const ulonglong2*)(Q + (((size_t)b*LL + l)*HH + h)*DD);
    u64 q[32];
    #pragma unroll
    for (int i = 0; i < 16; i++) { ulonglong2 t = qp[i]; q[2*i] = t.x; q[2*i+1] = t.y; }

    float mx = -CUDART_INF_F, sm = 0.f;
    for (int s = 0; s < S; s++) {
        const ulonglong2* kp = (const ulonglong2*)(sK2 + s*DD);
        u64 acc[4] = {0ull, 0ull, 0ull, 0ull};
        #pragma unroll
        for (int i = 0; i < 16; i++) {
            ulonglong2 kv = kp[i];
            fma2(acc[(2*i) & 3], q[2*i],   kv.x);
            fma2(acc[(2*i+1) & 3], q[2*i+1], kv.y);
        }
        float2 f0 = unpack2(acc[0]), f1 = unpack2(acc[1]);
        float2 f2 = unpack2(acc[2]), f3 = unpack2(acc[3]);
        float dot = ((f0.x + f1.x) + (f2.x + f3.x)) + ((f0.y + f1.y) + (f2.y + f3.y));
        mx = fmaxf(mx, dot);
        sm += dot;
    }
    g_M[bh*LL + l] = mx - sm * (1.0f / (float)LL);
}

// ---------------- K2: per-(b,h) top-45 of M ----------------
__global__ __launch_bounds__(256) void k2_topk()
{
    __shared__ float sM[LL];
    __shared__ float rv[8];
    __shared__ int   ri[8];
    int bh = blockIdx.x;
    for (int i = threadIdx.x; i < LL; i += 256) {
        sM[i] = g_M[bh*LL + i];
        g_rank[bh*LL + i] = -1;
    }
    __syncthreads();

    int lane = threadIdx.x & 31, wid = threadIdx.x >> 5;
    for (int it = 0; it < UU; it++) {
        float bv = -CUDART_INF_F; int bi = 0x7fffffff;
        for (int i = threadIdx.x; i < LL; i += 256) {
            float v = sM[i];
            if (v > bv || (v == bv && i < bi)) { bv = v; bi = i; }
        }
        #pragma unroll
        for (int o = 16; o > 0; o >>= 1) {
            float ov = __shfl_down_sync(0xffffffffu, bv, o);
            int   oi = __shfl_down_sync(0xffffffffu, bi, o);
            if (ov > bv || (ov == bv && oi < bi)) { bv = ov; bi = oi; }
        }
        if (lane == 0) { rv[wid] = bv; ri[wid] = bi; }
        __syncthreads();
        if (threadIdx.x == 0) {
            for (int w = 1; w < 8; w++)
                if (rv[w] > bv || (rv[w] == bv && ri[w] < bi)) { bv = rv[w]; bi = ri[w]; }
            g_Mtop[bh*UU + it] = bi;
            g_rank[bh*LL + bi] = it;
            sM[bi] = -CUDART_INF_F;
        }
        __syncthreads();
    }
}

// ---------------- K3: flash-style attention for the 45 selected rows ----------------
// Queries are sorted ascending by position; finished q-groups skip all compute.
__global__ __launch_bounds__(256) void k3_attn(const float* __restrict__ Kg,
                                               const float* __restrict__ Vg,
                                               const float* __restrict__ Qg)
{
    __shared__ __align__(16) float sQ[TQ*SP];
    __shared__ __align__(16) float sKV[TK*SP];
    __shared__ __align__(16) float sS[TQ*SP];
    __shared__ float s_m[TQ], s_l[TQ], s_c[TQ];
    __shared__ int   s_qi0[TQ];   // unsorted
    __shared__ int   s_qi[TQ];    // sorted ascending
    __shared__ int   s_ou[TQ];    // original u for sorted slot

    int bh = blockIdx.x;
    int b = bh >> 3, h = bh & 7;
    int tid = threadIdx.x;

    if (tid < TQ) {
        s_qi0[tid] = (tid < UU) ? g_Mtop[bh*UU + tid] : -1;
        s_m[tid] = -CUDART_INF_F;
        s_l[tid] = 0.f;
    }
    __syncthreads();
    // parallel rank sort (ascending by qi, tie by original index)
    if (tid < TQ) {
        int qi = s_qi0[tid];
        int r = 0;
        #pragma unroll
        for (int j = 0; j < TQ; j++) {
            int qj = s_qi0[j];
            r += (qj < qi) || (qj == qi && j < tid);
        }
        s_qi[r] = qi;
        s_ou[r] = tid;
    }
    __syncthreads();
    int maxq = s_qi[TQ-1];

    // load Q rows (sorted order)
    for (int i = tid; i < TQ*16; i += 256) {
        int q = i >> 4, dv = i & 15;
        int row = s_qi[q];
        float4 v = make_float4(0.f, 0.f, 0.f, 0.f);
        if (row >= 0)
            v = ((const float4*)(Qg + (((size_t)b*LL + row)*HH + h)*DD))[dv];
        ((float4*)(sQ + q*SP))[dv] = v;
    }
    __syncthreads();

    int qg = tid >> 4, lg = tid & 15;
    int q0 = qg*3, k0 = lg*4, d0g = lg;

    u64 o0[3], o1[3];
    #pragma unroll
    for (int j = 0; j < 3; j++) { o0[j] = 0ull; o1[j] = 0ull; }

    const float scale = 0.125f;

    for (int t0 = 0; t0 < LL; t0 += TK) {
        if (t0 > maxq) break;
        // group active iff its largest qidx is still >= t0 (sorted ascending)
        bool gact = (s_qi[q0+2] >= t0);

        // ---- load K tile ----
        for (int i = tid; i < TK*16; i += 256) {
            int r = i >> 4, dv = i & 15;
            ((float4*)(sKV + r*SP))[dv] =
                ((const float4*)(Kg + (((size_t)b*LL + t0 + r)*HH + h)*DD))[dv];
        }
        __syncthreads();

        // ---- QK scores for active groups ----
        if (gact) {
            u64 aA[3][4], aB[3][4];
            #pragma unroll
            for (int j = 0; j < 3; j++)
                #pragma unroll
                for (int t = 0; t < 4; t++) { aA[j][t] = 0ull; aB[j][t] = 0ull; }
            #pragma unroll
            for (int dv = 0; dv < 16; dv++) {
                ulonglong2 qv[3];
                #pragma unroll
                for (int j = 0; j < 3; j++)
                    qv[j] = ((const ulonglong2*)(sQ + (q0+j)*SP))[dv];
                ulonglong2 kv[4];
                #pragma unroll
                for (int t = 0; t < 4; t++)
                    kv[t] = ((const ulonglong2*)(sKV + (k0+t)*SP))[dv];
                #pragma unroll
                for (int j = 0; j < 3; j++)
                    #pragma unroll
                    for (int t = 0; t < 4; t++) {
                        fma2(aA[j][t], qv[j].x, kv[t].x);
                        fma2(aB[j][t], qv[j].y, kv[t].y);
                    }
            }
            #pragma unroll
            for (int j = 0; j < 3; j++)
                #pragma unroll
                for (int t = 0; t < 4; t++) {
                    float2 fa = unpack2(aA[j][t]);
                    float2 fb = unpack2(aB[j][t]);
                    sS[(q0+j)*SP + k0 + t] = ((fa.x + fa.y) + (fb.x + fb.y)) * scale;
                }
        }
        __syncthreads();

        // ---- load V tile + stats ----
        for (int i = tid; i < TK*16; i += 256) {
            int r = i >> 4, dv = i & 15;
            ((float4*)(sKV + r*SP))[dv] =
                ((const float4*)(Vg + (((size_t)b*LL + t0 + r)*HH + h)*DD))[dv];
        }
        if (tid < TQ) {
            int qi = s_qi[tid];
            int vlim = qi - t0;
            float tm = -CUDART_INF_F;
            if (vlim >= 0) {
                int n = min(vlim + 1, TK);
                for (int k = 0; k < n; k++) tm = fmaxf(tm, sS[tid*SP + k]);
            }
            float m_old = s_m[tid];
            float m_new = fmaxf(m_old, tm);
            float c = (m_new == -CUDART_INF_F) ? 1.f : __expf(m_old - m_new);
            s_c[tid] = c;
            s_m[tid] = m_new;
        }
        __syncthreads();

        // ---- exp pass (active groups; finished members get p=0) ----
        if (gact) {
            #pragma unroll
            for (int j = 0; j < 3; j++) {
                int q = q0 + j;
                int qi = s_qi[q];
                float mq = s_m[q];
                #pragma unroll
                for (int t = 0; t < 4; t++) {
                    int k = k0 + t;
                    float sval = sS[q*SP + k];
                    float p = 0.f;
                    if ((t0 + k) <= qi && mq != -CUDART_INF_F) p = __expf(sval - mq);
                    sS[q*SP + k] = p;
                }
            }
        }
        __syncthreads();

        // ---- l update (only still-active queries) ----
        if (tid < TQ && s_qi[tid] >= t0) {
            float sum = 0.f;
            for (int k = 0; k < TK; k++) sum += sS[tid*SP + k];
            s_l[tid] = s_l[tid]*s_c[tid] + sum;
        }
        __syncthreads();

        // ---- rescale O + PV accumulate (active groups) ----
        if (gact) {
            #pragma unroll
            for (int j = 0; j < 3; j++) {
                float c = s_c[q0 + j];
                u64 cp = pack2(c, c);
                mul2(o0[j], o0[j], cp);
                mul2(o1[j], o1[j], cp);
            }
            for (int kb = 0; kb < TK; kb += 4) {
                float4 sv[3];
                #pragma unroll
                for (int j = 0; j < 3; j++)
                    sv[j] = *(const float4*)(sS + (q0+j)*SP + kb);
                ulonglong2 vv[4];
                #pragma unroll
                for (int t = 0; t < 4; t++)
                    vv[t] = ((const ulonglong2*)(sKV + (kb+t)*SP))[d0g];
                #pragma unroll
                for (int j = 0; j < 3; j++) {
                    float sj[4] = {sv[j].x, sv[j].y, sv[j].z, sv[j].w};
                    #pragma unroll
                    for (int t = 0; t < 4; t++) {
                        u64 sp = pack2(sj[t], sj[t]);
                        fma2(o0[j], sp, vv[t].x);
                        fma2(o1[j], sp, vv[t].y);
                    }
                }
            }
        }
        __syncthreads();
    }

    // ---- epilogue ----
    #pragma unroll
    for (int j = 0; j < 3; j++) {
        int q = q0 + j;
        int ou = s_ou[q];
        if (ou < UU && s_qi[q] >= 0) {
            float inv = 1.f / s_l[q];
            float2 a = unpack2(o0[j]);
            float2 c = unpack2(o1[j]);
            float* dst = g_ctx + (bh*UU + ou)*DD + d0g*4;
            dst[0] = a.x*inv; dst[1] = a.y*inv;
            dst[2] = c.x*inv; dst[3] = c.y*inv;
        }
    }
}

// ---------------- K4: per-chunk V sums (vectorized) ----------------
__global__ __launch_bounds__(256) void k4_csum(const float* __restrict__ Vg)
{
    __shared__ float sp[16][64];
    int c = blockIdx.x, bh = blockIdx.y, b = bh >> 3, h = bh & 7;
    int qd = threadIdx.x & 15, rg = threadIdx.x >> 4;
    int l0 = c * CLEN;
    float4 acc = make_float4(0.f, 0.f, 0.f, 0.f);
    #pragma unroll
    for (int t = 0; t < 4; t++) {
        int l = l0 + rg + t*16;
        float4 v = ((const float4*)(Vg + (((size_t)b*LL + l)*HH + h)*DD))[qd];
        acc.x += v.x; acc.y += v.y; acc.z += v.z; acc.w += v.w;
    }
    *(float4*)&sp[rg][qd*4] = acc;
    __syncthreads();
    if (threadIdx.x < 64) {
        int d = threadIdx.x;
        float s = 0.f;
        #pragma unroll
        for (int r = 0; r < 16; r++) s += sp[r][d];
        g_csum[(bh*NC + c)*DD + d] = s;
    }
}

// ---------------- K5: scan + scatter (vectorized, rank in smem) ----------------
__global__ __launch_bounds__(256) void k5_scan(const float* __restrict__ Vg,
                                               float* __restrict__ out)
{
    __shared__ int srank[1024];
    int bh = blockIdx.y, b = bh >> 3, h = bh & 7;
    int qd = threadIdx.x & 15, cl = threadIdx.x >> 4;
    int c = blockIdx.x * 16 + cl;
    int base_l = blockIdx.x * 1024;

    for (int i = threadIdx.x; i < 1024; i += 256)
        srank[i] = g_rank[bh*LL + base_l + i];
    __syncthreads();

    float4 acc = make_float4(0.f, 0.f, 0.f, 0.f);
    for (int cc = 0; cc < c; cc++) {
        float4 v = ((const float4*)(g_csum + (bh*NC + cc)*DD))[qd];
        acc.x += v.x; acc.y += v.y; acc.z += v.z; acc.w += v.w;
    }

    int l0 = c * CLEN;
    #pragma unroll 4
    for (int j = 0; j < CLEN; j++) {
        int l = l0 + j;
        float4 v = ((const float4*)(Vg + (((size_t)b*LL + l)*HH + h)*DD))[qd];
        acc.x += v.x; acc.y += v.y; acc.z += v.z; acc.w += v.w;
        float4 o = acc;
        int r = srank[l - base_l];
        if (r >= 0)
            o = ((const float4*)(g_ctx + (bh*UU + r)*DD))[qd];
        ((float4*)(out + (((size_t)b*LL + l)*HH + h)*DD))[qd] = o;
    }
}

extern "C" void kernel_launch(void* const* d_in, const int* in_sizes, int n_in,
                              void* d_out, int out_size)
{
    const float* Q    = (const float*)d_in[0];
    const float* K    = (const float*)d_in[1];
    const float* V    = (const float*)d_in[2];
    const int*   idxk = (const int*)d_in[3];
    int S = in_sizes[3];
    float* out = (float*)d_out;

    k1_M   <<<dim3(LL/256, BH), 256>>>(Q, K, idxk, S);
    k2_topk<<<BH, 256>>>();
    k3_attn<<<BH, 256>>>(K, V, Q);
    k4_csum<<<dim3(NC, BH), 256>>>(V);
    k5_scan<<<dim3(NC/16, BH), 256>>>(V, out);
}

// round 4
// speedup vs baseline: 1.8305x; 1.2124x over previous
#include <cuda_runtime.h>
#include <math_constants.h>

#define BB 16
#define LL 4096
#define HH 8
#define DD 64
#define BH (BB*HH)     // 128
#define UU 45
#define NC 64
#define CLEN 64        // LL/NC

#define TQ 48          // queries padded (45 real + 3 dummy)
#define TK 64          // key tile
#define SP 68          // padded smem row stride in floats
#define NSPLIT 8
#define KS (LL/NSPLIT) // 512 keys per split

typedef unsigned long long u64;

__device__ __forceinline__ void fma2(u64 &d, u64 a, u64 b){
    asm("fma.rn.f32x2 %0, %1, %2, %0;" : "+l"(d) : "l"(a), "l"(b));
}
__device__ __forceinline__ u64 pack2(float x, float y){
    u64 r; asm("mov.b64 %0, {%1, %2};" : "=l"(r) : "f"(x), "f"(y)); return r;
}
__device__ __forceinline__ float2 unpack2(u64 v){
    float2 r; asm("mov.b64 {%0, %1}, %2;" : "=f"(r.x), "=f"(r.y) : "l"(v)); return r;
}
__device__ __forceinline__ void mul2(u64 &d, u64 a, u64 b){
    asm("mul.rn.f32x2 %0, %1, %2;" : "=l"(d) : "l"(a), "l"(b));
}

// static scratch (no allocs allowed)
__device__ float g_M[BH*LL];
__device__ int   g_Mtop[BH*UU];
__device__ int   g_rank[BH*LL];
__device__ float g_ctx[BH*UU*DD];
__device__ float g_csum[BH*NC*DD];
__device__ float g_pm[BH*NSPLIT*TQ];       // split partial max
__device__ float g_pl[BH*NSPLIT*TQ];       // split partial l
__device__ float g_po[BH*NSPLIT*TQ*DD];    // split partial O (unnormalized)

// ---------------- K1: M[bh][l] = max_s(Q_l . K2_s) - sum_s(Q_l . K2_s)/L ----------------
__global__ __launch_bounds__(256) void k1_M(const float* __restrict__ Q,
                                            const float* __restrict__ K,
                                            const int* __restrict__ idxk, int S)
{
    __shared__ __align__(16) float sK2[UU*DD];
    int bh = blockIdx.y;
    int b = bh >> 3, h = bh & 7;
    for (int i = threadIdx.x; i < S*DD; i += 256) {
        int s = i >> 6, d = i & 63;
        int kk = idxk[s];
        float v = K[(((size_t)b*LL + kk)*HH + h)*DD + d];
        sK2[i] = v * v;
    }
    __syncthreads();

    int l = blockIdx.x * 256 + threadIdx.x;
    const ulonglong2* qp = (const ulonglong2*)(Q + (((size_t)b*LL + l)*HH + h)*DD);
    u64 q[32];
    #pragma unroll
    for (int i = 0; i < 16; i++) { ulonglong2 t = qp[i]; q[2*i] = t.x; q[2*i+1] = t.y; }

    float mx = -CUDART_INF_F, sm = 0.f;
    for (int s = 0; s < S; s++) {
        const ulonglong2* kp = (const ulonglong2*)(sK2 + s*DD);
        u64 acc[4] = {0ull, 0ull, 0ull, 0ull};
        #pragma unroll
        for (int i = 0; i < 16; i++) {
            ulonglong2 kv = kp[i];
            fma2(acc[(2*i) & 3], q[2*i],   kv.x);
            fma2(acc[(2*i+1) & 3], q[2*i+1], kv.y);
        }
        float2 f0 = unpack2(acc[0]), f1 = unpack2(acc[1]);
        float2 f2 = unpack2(acc[2]), f3 = unpack2(acc[3]);
        float dot = ((f0.x + f1.x) + (f2.x + f3.x)) + ((f0.y + f1.y) + (f2.y + f3.y));
        mx = fmaxf(mx, dot);
        sm += dot;
    }
    g_M[bh*LL + l] = mx - sm * (1.0f / (float)LL);
}

// ---------------- K2: per-(b,h) top-45 of M ----------------
__global__ __launch_bounds__(256) void k2_topk()
{
    __shared__ float sM[LL];
    __shared__ float rv[8];
    __shared__ int   ri[8];
    int bh = blockIdx.x;
    for (int i = threadIdx.x; i < LL; i += 256) {
        sM[i] = g_M[bh*LL + i];
        g_rank[bh*LL + i] = -1;
    }
    __syncthreads();

    int lane = threadIdx.x & 31, wid = threadIdx.x >> 5;
    for (int it = 0; it < UU; it++) {
        float bv = -CUDART_INF_F; int bi = 0x7fffffff;
        for (int i = threadIdx.x; i < LL; i += 256) {
            float v = sM[i];
            if (v > bv || (v == bv && i < bi)) { bv = v; bi = i; }
        }
        #pragma unroll
        for (int o = 16; o > 0; o >>= 1) {
            float ov = __shfl_down_sync(0xffffffffu, bv, o);
            int   oi = __shfl_down_sync(0xffffffffu, bi, o);
            if (ov > bv || (ov == bv && oi < bi)) { bv = ov; bi = oi; }
        }
        if (lane == 0) { rv[wid] = bv; ri[wid] = bi; }
        __syncthreads();
        if (threadIdx.x == 0) {
            for (int w = 1; w < 8; w++)
                if (rv[w] > bv || (rv[w] == bv && ri[w] < bi)) { bv = rv[w]; bi = ri[w]; }
            g_Mtop[bh*UU + it] = bi;
            g_rank[bh*LL + bi] = it;
            sM[bi] = -CUDART_INF_F;
        }
        __syncthreads();
    }
}

// ---------------- K3: split-K flash attention partials ----------------
// grid (NSPLIT, BH). Keys [split*KS, split*KS+KS). Queries sorted ascending.
__global__ __launch_bounds__(256) void k3_attn(const float* __restrict__ Kg,
                                               const float* __restrict__ Vg,
                                               const float* __restrict__ Qg)
{
    __shared__ __align__(16) float sQ[TQ*SP];
    __shared__ __align__(16) float sKV[TK*SP];
    __shared__ __align__(16) float sS[TQ*SP];
    __shared__ float s_m[TQ], s_l[TQ], s_c[TQ];
    __shared__ int   s_qi0[TQ];
    __shared__ int   s_qi[TQ];
    __shared__ int   s_ou[TQ];

    int split = blockIdx.x;
    int bh = blockIdx.y;
    int b = bh >> 3, h = bh & 7;
    int tid = threadIdx.x;
    int ks = split * KS;

    if (tid < TQ) {
        s_qi0[tid] = (tid < UU) ? g_Mtop[bh*UU + tid] : -1;
        s_m[tid] = -CUDART_INF_F;
        s_l[tid] = 0.f;
    }
    __syncthreads();
    if (tid < TQ) {
        int qi = s_qi0[tid];
        int r = 0;
        #pragma unroll
        for (int j = 0; j < TQ; j++) {
            int qj = s_qi0[j];
            r += (qj < qi) || (qj == qi && j < tid);
        }
        s_qi[r] = qi;
        s_ou[r] = tid;
    }
    __syncthreads();
    int maxq = s_qi[TQ-1];

    for (int i = tid; i < TQ*16; i += 256) {
        int q = i >> 4, dv = i & 15;
        int row = s_qi[q];
        float4 v = make_float4(0.f, 0.f, 0.f, 0.f);
        if (row >= 0)
            v = ((const float4*)(Qg + (((size_t)b*LL + row)*HH + h)*DD))[dv];
        ((float4*)(sQ + q*SP))[dv] = v;
    }
    __syncthreads();

    int qg = tid >> 4, lg = tid & 15;
    int q0 = qg*3, d0g = lg;

    u64 o0[3], o1[3];
    #pragma unroll
    for (int j = 0; j < 3; j++) { o0[j] = 0ull; o1[j] = 0ull; }

    const float scale = 0.125f;
    int tend = min(ks + KS, maxq + 1);

    for (int t0 = ks; t0 < tend; t0 += TK) {
        bool gact = (s_qi[q0+2] >= t0);

        // ---- load K tile ----
        for (int i = tid; i < TK*16; i += 256) {
            int r = i >> 4, dv = i & 15;
            ((float4*)(sKV + r*SP))[dv] =
                ((const float4*)(Kg + (((size_t)b*LL + t0 + r)*HH + h)*DD))[dv];
        }
        __syncthreads();

        // ---- QK: rows k = lg + 16*t (conflict-free smem phases) ----
        if (gact) {
            u64 aA[3][4], aB[3][4];
            #pragma unroll
            for (int j = 0; j < 3; j++)
                #pragma unroll
                for (int t = 0; t < 4; t++) { aA[j][t] = 0ull; aB[j][t] = 0ull; }
            #pragma unroll
            for (int dv = 0; dv < 16; dv++) {
                ulonglong2 qv[3];
                #pragma unroll
                for (int j = 0; j < 3; j++)
                    qv[j] = ((const ulonglong2*)(sQ + (q0+j)*SP))[dv];
                ulonglong2 kv[4];
                #pragma unroll
                for (int t = 0; t < 4; t++)
                    kv[t] = ((const ulonglong2*)(sKV + (lg + 16*t)*SP))[dv];
                #pragma unroll
                for (int j = 0; j < 3; j++)
                    #pragma unroll
                    for (int t = 0; t < 4; t++) {
                        fma2(aA[j][t], qv[j].x, kv[t].x);
                        fma2(aB[j][t], qv[j].y, kv[t].y);
                    }
            }
            #pragma unroll
            for (int j = 0; j < 3; j++)
                #pragma unroll
                for (int t = 0; t < 4; t++) {
                    float2 fa = unpack2(aA[j][t]);
                    float2 fb = unpack2(aB[j][t]);
                    sS[(q0+j)*SP + lg + 16*t] = ((fa.x + fa.y) + (fb.x + fb.y)) * scale;
                }
        }
        __syncthreads();

        // ---- load V tile + per-query stats ----
        for (int i = tid; i < TK*16; i += 256) {
            int r = i >> 4, dv = i & 15;
            ((float4*)(sKV + r*SP))[dv] =
                ((const float4*)(Vg + (((size_t)b*LL + t0 + r)*HH + h)*DD))[dv];
        }
        if (tid < TQ) {
            int qi = s_qi[tid];
            int vlim = qi - t0;
            float tm = -CUDART_INF_F;
            if (vlim >= 0) {
                int n = min(vlim + 1, TK);
                for (int k = 0; k < n; k++) tm = fmaxf(tm, sS[tid*SP + k]);
            }
            float m_old = s_m[tid];
            float m_new = fmaxf(m_old, tm);
            float c = (m_new == -CUDART_INF_F) ? 1.f : __expf(m_old - m_new);
            s_c[tid] = c;
            s_m[tid] = m_new;
        }
        __syncthreads();

        // ---- exp pass (P = exp(S - m), causal masked) ----
        if (gact) {
            #pragma unroll
            for (int j = 0; j < 3; j++) {
                int q = q0 + j;
                int qi = s_qi[q];
                float mq = s_m[q];
                #pragma unroll
                for (int t = 0; t < 4; t++) {
                    int k = lg + 16*t;
                    float sval = sS[q*SP + k];
                    float p = 0.f;
                    if ((t0 + k) <= qi && mq != -CUDART_INF_F) p = __expf(sval - mq);
                    sS[q*SP + k] = p;
                }
            }
        }
        __syncthreads();

        // ---- l update ----
        if (tid < TQ && s_qi[tid] >= t0) {
            float sum = 0.f;
            for (int k = 0; k < TK; k++) sum += sS[tid*SP + k];
            s_l[tid] = s_l[tid]*s_c[tid] + sum;
        }
        __syncthreads();

        // ---- rescale O + PV accumulate ----
        if (gact) {
            #pragma unroll
            for (int j = 0; j < 3; j++) {
                float c = s_c[q0 + j];
                u64 cp = pack2(c, c);
                mul2(o0[j], o0[j], cp);
                mul2(o1[j], o1[j], cp);
            }
            for (int kb = 0; kb < TK; kb += 4) {
                float4 sv[3];
                #pragma unroll
                for (int j = 0; j < 3; j++)
                    sv[j] = *(const float4*)(sS + (q0+j)*SP + kb);
                ulonglong2 vv[4];
                #pragma unroll
                for (int t = 0; t < 4; t++)
                    vv[t] = ((const ulonglong2*)(sKV + (kb+t)*SP))[d0g];
                #pragma unroll
                for (int j = 0; j < 3; j++) {
                    float sj[4] = {sv[j].x, sv[j].y, sv[j].z, sv[j].w};
                    #pragma unroll
                    for (int t = 0; t < 4; t++) {
                        u64 sp = pack2(sj[t], sj[t]);
                        fma2(o0[j], sp, vv[t].x);
                        fma2(o1[j], sp, vv[t].y);
                    }
                }
            }
        }
        __syncthreads();
    }

    // ---- write partials (unnormalized O; m, l per query) ----
    int pbase = (bh*NSPLIT + split)*TQ;
    #pragma unroll
    for (int j = 0; j < 3; j++) {
        int q = q0 + j;
        int ou = s_ou[q];
        if (ou < UU && s_qi[q] >= 0) {
            float2 a = unpack2(o0[j]);
            float2 c = unpack2(o1[j]);
            ((float4*)(g_po + ((size_t)(pbase + ou))*DD))[d0g] =
                make_float4(a.x, a.y, c.x, c.y);
        }
    }
    if (tid < TQ && s_qi[tid] >= 0 && s_ou[tid] < UU) {
        g_pm[pbase + s_ou[tid]] = s_m[tid];
        g_pl[pbase + s_ou[tid]] = s_l[tid];
    }
}

// ---------------- K3c: combine split partials ----------------
__global__ __launch_bounds__(256) void k3c_combine()
{
    __shared__ float sf[UU][NSPLIT];
    int bh = blockIdx.x;
    int tid = threadIdx.x;
    if (tid < UU) {
        float mv[NSPLIT], lv[NSPLIT];
        float m = -CUDART_INF_F;
        #pragma unroll
        for (int s = 0; s < NSPLIT; s++) {
            mv[s] = g_pm[(bh*NSPLIT + s)*TQ + tid];
            lv[s] = g_pl[(bh*NSPLIT + s)*TQ + tid];
            m = fmaxf(m, mv[s]);
        }
        float l = 0.f;
        float w[NSPLIT];
        #pragma unroll
        for (int s = 0; s < NSPLIT; s++) {
            w[s] = (mv[s] == -CUDART_INF_F) ? 0.f : __expf(mv[s] - m);
            l += lv[s] * w[s];
        }
        float inv = 1.f / l;
        #pragma unroll
        for (int s = 0; s < NSPLIT; s++) sf[tid][s] = w[s] * inv;
    }
    __syncthreads();
    for (int idx = tid; idx < UU*16; idx += 256) {
        int q = idx >> 4, dv = idx & 15;
        float4 acc = make_float4(0.f, 0.f, 0.f, 0.f);
        #pragma unroll
        for (int s = 0; s < NSPLIT; s++) {
            float f = sf[q][s];
            float4 v = ((const float4*)(g_po + ((size_t)((bh*NSPLIT + s)*TQ + q))*DD))[dv];
            acc.x += f*v.x; acc.y += f*v.y; acc.z += f*v.z; acc.w += f*v.w;
        }
        ((float4*)(g_ctx + (bh*UU + q)*DD))[dv] = acc;
    }
}

// ---------------- K4: per-chunk V sums (vectorized) ----------------
__global__ __launch_bounds__(256) void k4_csum(const float* __restrict__ Vg)
{
    __shared__ float sp[16][64];
    int c = blockIdx.x, bh = blockIdx.y, b = bh >> 3, h = bh & 7;
    int qd = threadIdx.x & 15, rg = threadIdx.x >> 4;
    int l0 = c * CLEN;
    float4 acc = make_float4(0.f, 0.f, 0.f, 0.f);
    #pragma unroll
    for (int t = 0; t < 4; t++) {
        int l = l0 + rg + t*16;
        float4 v = ((const float4*)(Vg + (((size_t)b*LL + l)*HH + h)*DD))[qd];
        acc.x += v.x; acc.y += v.y; acc.z += v.z; acc.w += v.w;
    }
    *(float4*)&sp[rg][qd*4] = acc;
    __syncthreads();
    if (threadIdx.x < 64) {
        int d = threadIdx.x;
        float s = 0.f;
        #pragma unroll
        for (int r = 0; r < 16; r++) s += sp[r][d];
        g_csum[(bh*NC + c)*DD + d] = s;
    }
}

// ---------------- K5: scan + scatter (vectorized, rank in smem) ----------------
__global__ __launch_bounds__(256) void k5_scan(const float* __restrict__ Vg,
                                               float* __restrict__ out)
{
    __shared__ int srank[1024];
    int bh = blockIdx.y, b = bh >> 3, h = bh & 7;
    int qd = threadIdx.x & 15, cl = threadIdx.x >> 4;
    int c = blockIdx.x * 16 + cl;
    int base_l = blockIdx.x * 1024;

    for (int i = threadIdx.x; i < 1024; i += 256)
        srank[i] = g_rank[bh*LL + base_l + i];
    __syncthreads();

    float4 acc = make_float4(0.f, 0.f, 0.f, 0.f);
    for (int cc = 0; cc < c; cc++) {
        float4 v = ((const float4*)(g_csum + (bh*NC + cc)*DD))[qd];
        acc.x += v.x; acc.y += v.y; acc.z += v.z; acc.w += v.w;
    }

    int l0 = c * CLEN;
    #pragma unroll 4
    for (int j = 0; j < CLEN; j++) {
        int l = l0 + j;
        float4 v = ((const float4*)(Vg + (((size_t)b*LL + l)*HH + h)*DD))[qd];
        acc.x += v.x; acc.y += v.y; acc.z += v.z; acc.w += v.w;
        float4 o = acc;
        int r = srank[l - base_l];
        if (r >= 0)
            o = ((const float4*)(g_ctx + (bh*UU + r)*DD))[qd];
        ((float4*)(out + (((size_t)b*LL + l)*HH + h)*DD))[qd] = o;
    }
}

extern "C" void kernel_launch(void* const* d_in, const int* in_sizes, int n_in,
                              void* d_out, int out_size)
{
    const float* Q    = (const float*)d_in[0];
    const float* K    = (const float*)d_in[1];
    const float* V    = (const float*)d_in[2];
    const int*   idxk = (const int*)d_in[3];
    int S = in_sizes[3];
    float* out = (float*)d_out;

    k1_M   <<<dim3(LL/256, BH), 256>>>(Q, K, idxk, S);
    k2_topk<<<BH, 256>>>();
    k3_attn<<<dim3(NSPLIT, BH), 256>>>(K, V, Q);
    k3c_combine<<<BH, 256>>>();
    k4_csum<<<dim3(NC, BH), 256>>>(V);
    k5_scan<<<dim3(NC/16, BH), 256>>>(V, out);
}

// round 5
// speedup vs baseline: 2.5270x; 1.3805x over previous
#include <cuda_runtime.h>
#include <math_constants.h>

#define BB 16
#define LL 4096
#define HH 8
#define DD 64
#define BH (BB*HH)     // 128
#define UU 45
#define NC 64
#define CLEN 64        // LL/NC

#define TQ 48          // queries padded (45 real + 3 dummy)
#define TK 64          // key tile
#define SP 68          // padded smem row stride in floats
#define NSPLIT 16
#define KS (LL/NSPLIT) // 256 keys per split

typedef unsigned long long u64;

__device__ __forceinline__ void fma2(u64 &d, u64 a, u64 b){
    asm("fma.rn.f32x2 %0, %1, %2, %0;" : "+l"(d) : "l"(a), "l"(b));
}
__device__ __forceinline__ u64 pack2(float x, float y){
    u64 r; asm("mov.b64 %0, {%1, %2};" : "=l"(r) : "f"(x), "f"(y)); return r;
}
__device__ __forceinline__ float2 unpack2(u64 v){
    float2 r; asm("mov.b64 {%0, %1}, %2;" : "=f"(r.x), "=f"(r.y) : "l"(v)); return r;
}
__device__ __forceinline__ void mul2(u64 &d, u64 a, u64 b){
    asm("mul.rn.f32x2 %0, %1, %2;" : "=l"(d) : "l"(a), "l"(b));
}

// static scratch (no allocs allowed)
__device__ float g_M[BH*LL];
__device__ int   g_Mtop[BH*UU];
__device__ int   g_rank[BH*LL];
__device__ float g_ctx[BH*UU*DD];
__device__ float g_csum[BH*NC*DD];
__device__ float g_pm[BH*NSPLIT*TQ];
__device__ float g_pl[BH*NSPLIT*TQ];
__device__ float g_po[(size_t)BH*NSPLIT*TQ*DD];

// ---------------- K1 ----------------
__global__ __launch_bounds__(256) void k1_M(const float* __restrict__ Q,
                                            const float* __restrict__ K,
                                            const int* __restrict__ idxk, int S)
{
    __shared__ __align__(16) float sK2[UU*DD];
    int bh = blockIdx.y;
    int b = bh >> 3, h = bh & 7;
    for (int i = threadIdx.x; i < S*DD; i += 256) {
        int s = i >> 6, d = i & 63;
        int kk = idxk[s];
        float v = K[(((size_t)b*LL + kk)*HH + h)*DD + d];
        sK2[i] = v * v;
    }
    __syncthreads();

    int l = blockIdx.x * 256 + threadIdx.x;
    const ulonglong2* qp = (const ulonglong2*)(Q + (((size_t)b*LL + l)*HH + h)*DD);
    u64 q[32];
    #pragma unroll
    for (int i = 0; i < 16; i++) { ulonglong2 t = qp[i]; q[2*i] = t.x; q[2*i+1] = t.y; }

    float mx = -CUDART_INF_F, sm = 0.f;
    for (int s = 0; s < S; s++) {
        const ulonglong2* kp = (const ulonglong2*)(sK2 + s*DD);
        u64 acc[4] = {0ull, 0ull, 0ull, 0ull};
        #pragma unroll
        for (int i = 0; i < 16; i++) {
            ulonglong2 kv = kp[i];
            fma2(acc[(2*i) & 3], q[2*i],   kv.x);
            fma2(acc[(2*i+1) & 3], q[2*i+1], kv.y);
        }
        float2 f0 = unpack2(acc[0]), f1 = unpack2(acc[1]);
        float2 f2 = unpack2(acc[2]), f3 = unpack2(acc[3]);
        float dot = ((f0.x + f1.x) + (f2.x + f3.x)) + ((f0.y + f1.y) + (f2.y + f3.y));
        mx = fmaxf(mx, dot);
        sm += dot;
    }
    g_M[bh*LL + l] = mx - sm * (1.0f / (float)LL);
}

// ---------------- K2 ----------------
__global__ __launch_bounds__(256) void k2_topk()
{
    __shared__ float sM[LL];
    __shared__ float rv[8];
    __shared__ int   ri[8];
    int bh = blockIdx.x;
    for (int i = threadIdx.x; i < LL; i += 256) {
        sM[i] = g_M[bh*LL + i];
        g_rank[bh*LL + i] = -1;
    }
    __syncthreads();

    int lane = threadIdx.x & 31, wid = threadIdx.x >> 5;
    for (int it = 0; it < UU; it++) {
        float bv = -CUDART_INF_F; int bi = 0x7fffffff;
        for (int i = threadIdx.x; i < LL; i += 256) {
            float v = sM[i];
            if (v > bv || (v == bv && i < bi)) { bv = v; bi = i; }
        }
        #pragma unroll
        for (int o = 16; o > 0; o >>= 1) {
            float ov = __shfl_down_sync(0xffffffffu, bv, o);
            int   oi = __shfl_down_sync(0xffffffffu, bi, o);
            if (ov > bv || (ov == bv && oi < bi)) { bv = ov; bi = oi; }
        }
        if (lane == 0) { rv[wid] = bv; ri[wid] = bi; }
        __syncthreads();
        if (threadIdx.x == 0) {
            for (int w = 1; w < 8; w++)
                if (rv[w] > bv || (rv[w] == bv && ri[w] < bi)) { bv = rv[w]; bi = ri[w]; }
            g_Mtop[bh*UU + it] = bi;
            g_rank[bh*LL + bi] = it;
            sM[bi] = -CUDART_INF_F;
        }
        __syncthreads();
    }
}

// ---------------- K3: split-K flash, register softmax stats per half-warp group ----------------
__global__ __launch_bounds__(256) void k3_attn(const float* __restrict__ Kg,
                                               const float* __restrict__ Vg,
                                               const float* __restrict__ Qg)
{
    __shared__ __align__(16) float sQ[TQ*SP];
    __shared__ __align__(16) float sKV[TK*SP];
    __shared__ __align__(16) float sS[TQ*SP];
    __shared__ int s_qi0[TQ];
    __shared__ int s_qi[TQ];
    __shared__ int s_ou[TQ];

    int split = blockIdx.x;
    int bh = blockIdx.y;
    int b = bh >> 3, h = bh & 7;
    int tid = threadIdx.x;
    int ks = split * KS;

    if (tid < TQ) s_qi0[tid] = (tid < UU) ? g_Mtop[bh*UU + tid] : -1;
    __syncthreads();
    if (tid < TQ) {
        int qi = s_qi0[tid];
        int r = 0;
        #pragma unroll
        for (int j = 0; j < TQ; j++) {
            int qj = s_qi0[j];
            r += (qj < qi) || (qj == qi && j < tid);
        }
        s_qi[r] = qi;
        s_ou[r] = tid;
    }
    __syncthreads();
    int maxq = s_qi[TQ-1];

    for (int i = tid; i < TQ*16; i += 256) {
        int q = i >> 4, dv = i & 15;
        int row = s_qi[q];
        float4 v = make_float4(0.f, 0.f, 0.f, 0.f);
        if (row >= 0)
            v = ((const float4*)(Qg + (((size_t)b*LL + row)*HH + h)*DD))[dv];
        ((float4*)(sQ + q*SP))[dv] = v;
    }
    __syncthreads();

    int qg = tid >> 4, lg = tid & 15;
    int q0 = qg*3, d0g = lg;
    unsigned hm = 0xffffu << (tid & 16);   // half-warp mask for shuffles

    int qi_r[3];
    #pragma unroll
    for (int j = 0; j < 3; j++) qi_r[j] = s_qi[q0+j];
    int gmax = qi_r[2];

    float m_r[3] = {-CUDART_INF_F, -CUDART_INF_F, -CUDART_INF_F};
    float l_r[3] = {0.f, 0.f, 0.f};
    u64 o0[3] = {0ull,0ull,0ull}, o1[3] = {0ull,0ull,0ull};

    const float scale = 0.125f;
    int tend = min(ks + KS, maxq + 1);

    for (int t0 = ks; t0 < tend; t0 += TK) {
        bool gact = (gmax >= t0);

        // ---- load K tile ----
        for (int i = tid; i < TK*16; i += 256) {
            int r = i >> 4, dv = i & 15;
            ((float4*)(sKV + r*SP))[dv] =
                ((const float4*)(Kg + (((size_t)b*LL + t0 + r)*HH + h)*DD))[dv];
        }
        __syncthreads();

        float s[3][4];
        if (gact) {
            u64 a[3][4];
            #pragma unroll
            for (int j = 0; j < 3; j++)
                #pragma unroll
                for (int t = 0; t < 4; t++) a[j][t] = 0ull;
            #pragma unroll
            for (int dv = 0; dv < 16; dv++) {
                ulonglong2 qv[3];
                #pragma unroll
                for (int j = 0; j < 3; j++)
                    qv[j] = ((const ulonglong2*)(sQ + (q0+j)*SP))[dv];
                ulonglong2 kv[4];
                #pragma unroll
                for (int t = 0; t < 4; t++)
                    kv[t] = ((const ulonglong2*)(sKV + (lg + 16*t)*SP))[dv];
                #pragma unroll
                for (int j = 0; j < 3; j++)
                    #pragma unroll
                    for (int t = 0; t < 4; t++) {
                        fma2(a[j][t], qv[j].x, kv[t].x);
                        fma2(a[j][t], qv[j].y, kv[t].y);
                    }
            }
            #pragma unroll
            for (int j = 0; j < 3; j++)
                #pragma unroll
                for (int t = 0; t < 4; t++) {
                    float2 f = unpack2(a[j][t]);
                    float sv = (f.x + f.y) * scale;
                    // causal mask in-register
                    s[j][t] = ((t0 + lg + 16*t) <= qi_r[j]) ? sv : -CUDART_INF_F;
                }
        }
        __syncthreads();   // all K reads done before V overwrites

        // ---- load V tile (all threads) + register softmax stats (active groups) ----
        for (int i = tid; i < TK*16; i += 256) {
            int r = i >> 4, dv = i & 15;
            ((float4*)(sKV + r*SP))[dv] =
                ((const float4*)(Vg + (((size_t)b*LL + t0 + r)*HH + h)*DD))[dv];
        }
        float c_r[3];
        if (gact) {
            #pragma unroll
            for (int j = 0; j < 3; j++) {
                float mx = fmaxf(fmaxf(s[j][0], s[j][1]), fmaxf(s[j][2], s[j][3]));
                #pragma unroll
                for (int o = 8; o > 0; o >>= 1)
                    mx = fmaxf(mx, __shfl_xor_sync(hm, mx, o));
                float m_new = fmaxf(m_r[j], mx);
                float c = (m_new == -CUDART_INF_F) ? 1.f : __expf(m_r[j] - m_new);
                float rs = 0.f;
                #pragma unroll
                for (int t = 0; t < 4; t++) {
                    float p = (s[j][t] == -CUDART_INF_F) ? 0.f : __expf(s[j][t] - m_new);
                    sS[(q0+j)*SP + lg + 16*t] = p;
                    rs += p;
                }
                #pragma unroll
                for (int o = 8; o > 0; o >>= 1)
                    rs += __shfl_xor_sync(hm, rs, o);
                l_r[j] = l_r[j]*c + rs;
                m_r[j] = m_new;
                c_r[j] = c;
            }
            __syncwarp(hm);   // sS visible within owning half-warp
        }
        __syncthreads();      // V tile visible to all

        if (gact) {
            #pragma unroll
            for (int j = 0; j < 3; j++) {
                u64 cp = pack2(c_r[j], c_r[j]);
                mul2(o0[j], o0[j], cp);
                mul2(o1[j], o1[j], cp);
            }
            for (int kb = 0; kb < TK; kb += 4) {
                float4 sv[3];
                #pragma unroll
                for (int j = 0; j < 3; j++)
                    sv[j] = *(const float4*)(sS + (q0+j)*SP + kb);
                ulonglong2 vv[4];
                #pragma unroll
                for (int t = 0; t < 4; t++)
                    vv[t] = ((const ulonglong2*)(sKV + (kb+t)*SP))[d0g];
                #pragma unroll
                for (int j = 0; j < 3; j++) {
                    float sj[4] = {sv[j].x, sv[j].y, sv[j].z, sv[j].w};
                    #pragma unroll
                    for (int t = 0; t < 4; t++) {
                        u64 sp = pack2(sj[t], sj[t]);
                        fma2(o0[j], sp, vv[t].x);
                        fma2(o1[j], sp, vv[t].y);
                    }
                }
            }
        }
        __syncthreads();      // V reads done before next K load
    }

    // ---- write partials ----
    int pbase = (bh*NSPLIT + split)*TQ;
    #pragma unroll
    for (int j = 0; j < 3; j++) {
        int q = q0 + j;
        int ou = s_ou[q];
        if (ou < UU) {
            float2 a = unpack2(o0[j]);
            float2 c = unpack2(o1[j]);
            ((float4*)(g_po + ((size_t)(pbase + ou))*DD))[d0g] =
                make_float4(a.x, a.y, c.x, c.y);
            if (lg == 0) {
                g_pm[pbase + ou] = m_r[j];
                g_pl[pbase + ou] = l_r[j];
            }
        }
    }
}

// ---------------- K3c: combine split partials ----------------
__global__ __launch_bounds__(256) void k3c_combine()
{
    __shared__ float sf[UU][NSPLIT];
    int bh = blockIdx.x;
    int tid = threadIdx.x;
    if (tid < UU) {
        float mv[NSPLIT], lv[NSPLIT];
        float m = -CUDART_INF_F;
        #pragma unroll
        for (int s = 0; s < NSPLIT; s++) {
            mv[s] = g_pm[(bh*NSPLIT + s)*TQ + tid];
            lv[s] = g_pl[(bh*NSPLIT + s)*TQ + tid];
            m = fmaxf(m, mv[s]);
        }
        float l = 0.f;
        float w[NSPLIT];
        #pragma unroll
        for (int s = 0; s < NSPLIT; s++) {
            w[s] = (mv[s] == -CUDART_INF_F) ? 0.f : __expf(mv[s] - m);
            l += lv[s] * w[s];
        }
        float inv = 1.f / l;
        #pragma unroll
        for (int s = 0; s < NSPLIT; s++) sf[tid][s] = w[s] * inv;
    }
    __syncthreads();
    for (int idx = tid; idx < UU*16; idx += 256) {
        int q = idx >> 4, dv = idx & 15;
        float4 acc = make_float4(0.f, 0.f, 0.f, 0.f);
        #pragma unroll
        for (int s = 0; s < NSPLIT; s++) {
            float f = sf[q][s];
            float4 v = ((const float4*)(g_po + ((size_t)((bh*NSPLIT + s)*TQ + q))*DD))[dv];
            acc.x += f*v.x; acc.y += f*v.y; acc.z += f*v.z; acc.w += f*v.w;
        }
        ((float4*)(g_ctx + (bh*UU + q)*DD))[dv] = acc;
    }
}

// ---------------- K4 ----------------
__global__ __launch_bounds__(256) void k4_csum(const float* __restrict__ Vg)
{
    __shared__ float sp[16][64];
    int c = blockIdx.x, bh = blockIdx.y, b = bh >> 3, h = bh & 7;
    int qd = threadIdx.x & 15, rg = threadIdx.x >> 4;
    int l0 = c * CLEN;
    float4 acc = make_float4(0.f, 0.f, 0.f, 0.f);
    #pragma unroll
    for (int t = 0; t < 4; t++) {
        int l = l0 + rg + t*16;
        float4 v = ((const float4*)(Vg + (((size_t)b*LL + l)*HH + h)*DD))[qd];
        acc.x += v.x; acc.y += v.y; acc.z += v.z; acc.w += v.w;
    }
    *(float4*)&sp[rg][qd*4] = acc;
    __syncthreads();
    if (threadIdx.x < 64) {
        int d = threadIdx.x;
        float s = 0.f;
        #pragma unroll
        for (int r = 0; r < 16; r++) s += sp[r][d];
        g_csum[(bh*NC + c)*DD + d] = s;
    }
}

// ---------------- K5 ----------------
__global__ __launch_bounds__(256) void k5_scan(const float* __restrict__ Vg,
                                               float* __restrict__ out)
{
    __shared__ int srank[1024];
    int bh = blockIdx.y, b = bh >> 3, h = bh & 7;
    int qd = threadIdx.x & 15, cl = threadIdx.x >> 4;
    int c = blockIdx.x * 16 + cl;
    int base_l = blockIdx.x * 1024;

    for (int i = threadIdx.x; i < 1024; i += 256)
        srank[i] = g_rank[bh*LL + base_l + i];
    __syncthreads();

    float4 acc = make_float4(0.f, 0.f, 0.f, 0.f);
    for (int cc = 0; cc < c; cc++) {
        float4 v = ((const float4*)(g_csum + (bh*NC + cc)*DD))[qd];
        acc.x += v.x; acc.y += v.y; acc.z += v.z; acc.w += v.w;
    }

    int l0 = c * CLEN;
    #pragma unroll 4
    for (int j = 0; j < CLEN; j++) {
        int l = l0 + j;
        float4 v = ((const float4*)(Vg + (((size_t)b*LL + l)*HH + h)*DD))[qd];
        acc.x += v.x; acc.y += v.y; acc.z += v.z; acc.w += v.w;
        float4 o = acc;
        int r = srank[l - base_l];
        if (r >= 0)
            o = ((const float4*)(g_ctx + (bh*UU + r)*DD))[qd];
        ((float4*)(out + (((size_t)b*LL + l)*HH + h)*DD))[qd] = o;
    }
}

extern "C" void kernel_launch(void* const* d_in, const int* in_sizes, int n_in,
                              void* d_out, int out_size)
{
    const float* Q    = (const float*)d_in[0];
    const float* K    = (const float*)d_in[1];
    const float* V    = (const float*)d_in[2];
    const int*   idxk = (const int*)d_in[3];
    int S = in_sizes[3];
    float* out = (float*)d_out;

    k1_M   <<<dim3(LL/256, BH), 256>>>(Q, K, idxk, S);
    k2_topk<<<BH, 256>>>();
    k3_attn<<<dim3(NSPLIT, BH), 256>>>(K, V, Q);
    k3c_combine<<<BH, 256>>>();
    k4_csum<<<dim3(NC, BH), 256>>>(V);
    k5_scan<<<dim3(NC/16, BH), 256>>>(V, out);
}

// round 6
// speedup vs baseline: 2.5285x; 1.0006x over previous
#include <cuda_runtime.h>
#include <math_constants.h>

#define BB 16
#define LL 4096
#define HH 8
#define DD 64
#define BH (BB*HH)     // 128
#define UU 45
#define NC 64
#define CLEN 64        // LL/NC

#define TQ 48          // queries padded (45 real + 3 dummy)
#define TK 64          // key tile
#define SP 68          // padded smem row stride in floats
#define NSPLIT 16
#define KS (LL/NSPLIT) // 256 keys per split

typedef unsigned long long u64;

__device__ __forceinline__ void fma2(u64 &d, u64 a, u64 b){
    asm("fma.rn.f32x2 %0, %1, %2, %0;" : "+l"(d) : "l"(a), "l"(b));
}
__device__ __forceinline__ u64 pack2(float x, float y){
    u64 r; asm("mov.b64 %0, {%1, %2};" : "=l"(r) : "f"(x), "f"(y)); return r;
}
__device__ __forceinline__ float2 unpack2(u64 v){
    float2 r; asm("mov.b64 {%0, %1}, %2;" : "=f"(r.x), "=f"(r.y) : "l"(v)); return r;
}
__device__ __forceinline__ void mul2(u64 &d, u64 a, u64 b){
    asm("mul.rn.f32x2 %0, %1, %2;" : "=l"(d) : "l"(a), "l"(b));
}

// static scratch (no allocs allowed)
__device__ float g_M[BH*LL];
__device__ int   g_Mtop[BH*UU];
__device__ int   g_rank[BH*LL];
__device__ float g_ctx[BH*UU*DD];
__device__ float g_csum[BH*NC*DD];
__device__ float g_pm[BH*NSPLIT*TQ];
__device__ float g_pl[BH*NSPLIT*TQ];
__device__ float g_po[(size_t)BH*NSPLIT*TQ*DD];

// ---------------- K1 ----------------
__global__ __launch_bounds__(256) void k1_M(const float* __restrict__ Q,
                                            const float* __restrict__ K,
                                            const int* __restrict__ idxk, int S)
{
    __shared__ __align__(16) float sK2[UU*DD];
    int bh = blockIdx.y;
    int b = bh >> 3, h = bh & 7;
    for (int i = threadIdx.x; i < S*DD; i += 256) {
        int s = i >> 6, d = i & 63;
        int kk = idxk[s];
        float v = K[(((size_t)b*LL + kk)*HH + h)*DD + d];
        sK2[i] = v * v;
    }
    __syncthreads();

    int l = blockIdx.x * 256 + threadIdx.x;
    const ulonglong2* qp = (const ulonglong2*)(Q + (((size_t)b*LL + l)*HH + h)*DD);
    u64 q[32];
    #pragma unroll
    for (int i = 0; i < 16; i++) { ulonglong2 t = qp[i]; q[2*i] = t.x; q[2*i+1] = t.y; }

    float mx = -CUDART_INF_F, sm = 0.f;
    for (int s = 0; s < S; s++) {
        const ulonglong2* kp = (const ulonglong2*)(sK2 + s*DD);
        u64 acc[4] = {0ull, 0ull, 0ull, 0ull};
        #pragma unroll
        for (int i = 0; i < 16; i++) {
            ulonglong2 kv = kp[i];
            fma2(acc[(2*i) & 3], q[2*i],   kv.x);
            fma2(acc[(2*i+1) & 3], q[2*i+1], kv.y);
        }
        float2 f0 = unpack2(acc[0]), f1 = unpack2(acc[1]);
        float2 f2 = unpack2(acc[2]), f3 = unpack2(acc[3]);
        float dot = ((f0.x + f1.x) + (f2.x + f3.x)) + ((f0.y + f1.y) + (f2.y + f3.y));
        mx = fmaxf(mx, dot);
        sm += dot;
    }
    g_M[bh*LL + l] = mx - sm * (1.0f / (float)LL);
}

// ---------------- K2 ----------------
__global__ __launch_bounds__(256) void k2_topk()
{
    __shared__ float sM[LL];
    __shared__ float rv[8];
    __shared__ int   ri[8];
    int bh = blockIdx.x;
    for (int i = threadIdx.x; i < LL; i += 256) {
        sM[i] = g_M[bh*LL + i];
        g_rank[bh*LL + i] = -1;
    }
    __syncthreads();

    int lane = threadIdx.x & 31, wid = threadIdx.x >> 5;
    for (int it = 0; it < UU; it++) {
        float bv = -CUDART_INF_F; int bi = 0x7fffffff;
        for (int i = threadIdx.x; i < LL; i += 256) {
            float v = sM[i];
            if (v > bv || (v == bv && i < bi)) { bv = v; bi = i; }
        }
        #pragma unroll
        for (int o = 16; o > 0; o >>= 1) {
            float ov = __shfl_down_sync(0xffffffffu, bv, o);
            int   oi = __shfl_down_sync(0xffffffffu, bi, o);
            if (ov > bv || (ov == bv && oi < bi)) { bv = ov; bi = oi; }
        }
        if (lane == 0) { rv[wid] = bv; ri[wid] = bi; }
        __syncthreads();
        if (threadIdx.x == 0) {
            for (int w = 1; w < 8; w++)
                if (rv[w] > bv || (rv[w] == bv && ri[w] < bi)) { bv = rv[w]; bi = ri[w]; }
            g_Mtop[bh*UU + it] = bi;
            g_rank[bh*LL + bi] = it;
            sM[bi] = -CUDART_INF_F;
        }
        __syncthreads();
    }
}

// ---------------- K3: split-K flash, register softmax stats per half-warp group ----------------
__global__ __launch_bounds__(256) void k3_attn(const float* __restrict__ Kg,
                                               const float* __restrict__ Vg,
                                               const float* __restrict__ Qg)
{
    __shared__ __align__(16) float sQ[TQ*SP];
    __shared__ __align__(16) float sKV[TK*SP];
    __shared__ __align__(16) float sS[TQ*SP];
    __shared__ int s_qi0[TQ];
    __shared__ int s_qi[TQ];
    __shared__ int s_ou[TQ];

    int split = blockIdx.x;
    int bh = blockIdx.y;
    int b = bh >> 3, h = bh & 7;
    int tid = threadIdx.x;
    int ks = split * KS;

    if (tid < TQ) s_qi0[tid] = (tid < UU) ? g_Mtop[bh*UU + tid] : -1;
    __syncthreads();
    if (tid < TQ) {
        int qi = s_qi0[tid];
        int r = 0;
        #pragma unroll
        for (int j = 0; j < TQ; j++) {
            int qj = s_qi0[j];
            r += (qj < qi) || (qj == qi && j < tid);
        }
        s_qi[r] = qi;
        s_ou[r] = tid;
    }
    __syncthreads();
    int maxq = s_qi[TQ-1];

    for (int i = tid; i < TQ*16; i += 256) {
        int q = i >> 4, dv = i & 15;
        int row = s_qi[q];
        float4 v = make_float4(0.f, 0.f, 0.f, 0.f);
        if (row >= 0)
            v = ((const float4*)(Qg + (((size_t)b*LL + row)*HH + h)*DD))[dv];
        ((float4*)(sQ + q*SP))[dv] = v;
    }
    __syncthreads();

    int qg = tid >> 4, lg = tid & 15;
    int q0 = qg*3, d0g = lg;
    unsigned hm = 0xffffu << (tid & 16);   // half-warp mask for shuffles

    int qi_r[3];
    #pragma unroll
    for (int j = 0; j < 3; j++) qi_r[j] = s_qi[q0+j];
    int gmax = qi_r[2];

    float m_r[3] = {-CUDART_INF_F, -CUDART_INF_F, -CUDART_INF_F};
    float l_r[3] = {0.f, 0.f, 0.f};
    u64 o0[3] = {0ull,0ull,0ull}, o1[3] = {0ull,0ull,0ull};

    const float scale = 0.125f;
    int tend = min(ks + KS, maxq + 1);

    for (int t0 = ks; t0 < tend; t0 += TK) {
        bool gact = (gmax >= t0);

        // ---- load K tile ----
        for (int i = tid; i < TK*16; i += 256) {
            int r = i >> 4, dv = i & 15;
            ((float4*)(sKV + r*SP))[dv] =
                ((const float4*)(Kg + (((size_t)b*LL + t0 + r)*HH + h)*DD))[dv];
        }
        __syncthreads();

        float s[3][4];
        if (gact) {
            u64 a[3][4];
            #pragma unroll
            for (int j = 0; j < 3; j++)
                #pragma unroll
                for (int t = 0; t < 4; t++) a[j][t] = 0ull;
            #pragma unroll
            for (int dv = 0; dv < 16; dv++) {
                ulonglong2 qv[3];
                #pragma unroll
                for (int j = 0; j < 3; j++)
                    qv[j] = ((const ulonglong2*)(sQ + (q0+j)*SP))[dv];
                ulonglong2 kv[4];
                #pragma unroll
                for (int t = 0; t < 4; t++)
                    kv[t] = ((const ulonglong2*)(sKV + (lg + 16*t)*SP))[dv];
                #pragma unroll
                for (int j = 0; j < 3; j++)
                    #pragma unroll
                    for (int t = 0; t < 4; t++) {
                        fma2(a[j][t], qv[j].x, kv[t].x);
                        fma2(a[j][t], qv[j].y, kv[t].y);
                    }
            }
            #pragma unroll
            for (int j = 0; j < 3; j++)
                #pragma unroll
                for (int t = 0; t < 4; t++) {
                    float2 f = unpack2(a[j][t]);
                    float sv = (f.x + f.y) * scale;
                    // causal mask in-register
                    s[j][t] = ((t0 + lg + 16*t) <= qi_r[j]) ? sv : -CUDART_INF_F;
                }
        }
        __syncthreads();   // all K reads done before V overwrites

        // ---- load V tile (all threads) + register softmax stats (active groups) ----
        for (int i = tid; i < TK*16; i += 256) {
            int r = i >> 4, dv = i & 15;
            ((float4*)(sKV + r*SP))[dv] =
                ((const float4*)(Vg + (((size_t)b*LL + t0 + r)*HH + h)*DD))[dv];
        }
        float c_r[3];
        if (gact) {
            #pragma unroll
            for (int j = 0; j < 3; j++) {
                float mx = fmaxf(fmaxf(s[j][0], s[j][1]), fmaxf(s[j][2], s[j][3]));
                #pragma unroll
                for (int o = 8; o > 0; o >>= 1)
                    mx = fmaxf(mx, __shfl_xor_sync(hm, mx, o));
                float m_new = fmaxf(m_r[j], mx);
                float c = (m_new == -CUDART_INF_F) ? 1.f : __expf(m_r[j] - m_new);
                float rs = 0.f;
                #pragma unroll
                for (int t = 0; t < 4; t++) {
                    float p = (s[j][t] == -CUDART_INF_F) ? 0.f : __expf(s[j][t] - m_new);
                    sS[(q0+j)*SP + lg + 16*t] = p;
                    rs += p;
                }
                #pragma unroll
                for (int o = 8; o > 0; o >>= 1)
                    rs += __shfl_xor_sync(hm, rs, o);
                l_r[j] = l_r[j]*c + rs;
                m_r[j] = m_new;
                c_r[j] = c;
            }
            __syncwarp(hm);   // sS visible within owning half-warp
        }
        __syncthreads();      // V tile visible to all

        if (gact) {
            #pragma unroll
            for (int j = 0; j < 3; j++) {
                u64 cp = pack2(c_r[j], c_r[j]);
                mul2(o0[j], o0[j], cp);
                mul2(o1[j], o1[j], cp);
            }
            for (int kb = 0; kb < TK; kb += 4) {
                float4 sv[3];
                #pragma unroll
                for (int j = 0; j < 3; j++)
                    sv[j] = *(const float4*)(sS + (q0+j)*SP + kb);
                ulonglong2 vv[4];
                #pragma unroll
                for (int t = 0; t < 4; t++)
                    vv[t] = ((const ulonglong2*)(sKV + (kb+t)*SP))[d0g];
                #pragma unroll
                for (int j = 0; j < 3; j++) {
                    float sj[4] = {sv[j].x, sv[j].y, sv[j].z, sv[j].w};
                    #pragma unroll
                    for (int t = 0; t < 4; t++) {
                        u64 sp = pack2(sj[t], sj[t]);
                        fma2(o0[j], sp, vv[t].x);
                        fma2(o1[j], sp, vv[t].y);
                    }
                }
            }
        }
        __syncthreads();      // V reads done before next K load
    }

    // ---- write partials ----
    int pbase = (bh*NSPLIT + split)*TQ;
    #pragma unroll
    for (int j = 0; j < 3; j++) {
        int q = q0 + j;
        int ou = s_ou[q];
        if (ou < UU) {
            float2 a = unpack2(o0[j]);
            float2 c = unpack2(o1[j]);
            ((float4*)(g_po + ((size_t)(pbase + ou))*DD))[d0g] =
                make_float4(a.x, a.y, c.x, c.y);
            if (lg == 0) {
                g_pm[pbase + ou] = m_r[j];
                g_pl[pbase + ou] = l_r[j];
            }
        }
    }
}

// ---------------- K3c: combine split partials ----------------
__global__ __launch_bounds__(256) void k3c_combine()
{
    __shared__ float sf[UU][NSPLIT];
    int bh = blockIdx.x;
    int tid = threadIdx.x;
    if (tid < UU) {
        float mv[NSPLIT], lv[NSPLIT];
        float m = -CUDART_INF_F;
        #pragma unroll
        for (int s = 0; s < NSPLIT; s++) {
            mv[s] = g_pm[(bh*NSPLIT + s)*TQ + tid];
            lv[s] = g_pl[(bh*NSPLIT + s)*TQ + tid];
            m = fmaxf(m, mv[s]);
        }
        float l = 0.f;
        float w[NSPLIT];
        #pragma unroll
        for (int s = 0; s < NSPLIT; s++) {
            w[s] = (mv[s] == -CUDART_INF_F) ? 0.f : __expf(mv[s] - m);
            l += lv[s] * w[s];
        }
        float inv = 1.f / l;
        #pragma unroll
        for (int s = 0; s < NSPLIT; s++) sf[tid][s] = w[s] * inv;
    }
    __syncthreads();
    for (int idx = tid; idx < UU*16; idx += 256) {
        int q = idx >> 4, dv = idx & 15;
        float4 acc = make_float4(0.f, 0.f, 0.f, 0.f);
        #pragma unroll
        for (int s = 0; s < NSPLIT; s++) {
            float f = sf[q][s];
            float4 v = ((const float4*)(g_po + ((size_t)((bh*NSPLIT + s)*TQ + q))*DD))[dv];
            acc.x += f*v.x; acc.y += f*v.y; acc.z += f*v.z; acc.w += f*v.w;
        }
        ((float4*)(g_ctx + (bh*UU + q)*DD))[dv] = acc;
    }
}

// ---------------- K4 ----------------
__global__ __launch_bounds__(256) void k4_csum(const float* __restrict__ Vg)
{
    __shared__ float sp[16][64];
    int c = blockIdx.x, bh = blockIdx.y, b = bh >> 3, h = bh & 7;
    int qd = threadIdx.x & 15, rg = threadIdx.x >> 4;
    int l0 = c * CLEN;
    float4 acc = make_float4(0.f, 0.f, 0.f, 0.f);
    #pragma unroll
    for (int t = 0; t < 4; t++) {
        int l = l0 + rg + t*16;
        float4 v = ((const float4*)(Vg + (((size_t)b*LL + l)*HH + h)*DD))[qd];
        acc.x += v.x; acc.y += v.y; acc.z += v.z; acc.w += v.w;
    }
    *(float4*)&sp[rg][qd*4] = acc;
    __syncthreads();
    if (threadIdx.x < 64) {
        int d = threadIdx.x;
        float s = 0.f;
        #pragma unroll
        for (int r = 0; r < 16; r++) s += sp[r][d];
        g_csum[(bh*NC + c)*DD + d] = s;
    }
}

// ---------------- K5 ----------------
__global__ __launch_bounds__(256) void k5_scan(const float* __restrict__ Vg,
                                               float* __restrict__ out)
{
    __shared__ int srank[1024];
    int bh = blockIdx.y, b = bh >> 3, h = bh & 7;
    int qd = threadIdx.x & 15, cl = threadIdx.x >> 4;
    int c = blockIdx.x * 16 + cl;
    int base_l = blockIdx.x * 1024;

    for (int i = threadIdx.x; i < 1024; i += 256)
        srank[i] = g_rank[bh*LL + base_l + i];
    __syncthreads();

    float4 acc = make_float4(0.f, 0.f, 0.f, 0.f);
    for (int cc = 0; cc < c; cc++) {
        float4 v = ((const float4*)(g_csum + (bh*NC + cc)*DD))[qd];
        acc.x += v.x; acc.y += v.y; acc.z += v.z; acc.w += v.w;
    }

    int l0 = c * CLEN;
    #pragma unroll 4
    for (int j = 0; j < CLEN; j++) {
        int l = l0 + j;
        float4 v = ((const float4*)(Vg + (((size_t)b*LL + l)*HH + h)*DD))[qd];
        acc.x += v.x; acc.y += v.y; acc.z += v.z; acc.w += v.w;
        float4 o = acc;
        int r = srank[l - base_l];
        if (r >= 0)
            o = ((const float4*)(g_ctx + (bh*UU + r)*DD))[qd];
        ((float4*)(out + (((size_t)b*LL + l)*HH + h)*DD))[qd] = o;
    }
}

extern "C" void kernel_launch(void* const* d_in, const int* in_sizes, int n_in,
                              void* d_out, int out_size)
{
    const float* Q    = (const float*)d_in[0];
    const float* K    = (const float*)d_in[1];
    const float* V    = (const float*)d_in[2];
    const int*   idxk = (const int*)d_in[3];
    int S = in_sizes[3];
    float* out = (float*)d_out;

    k1_M   <<<dim3(LL/256, BH), 256>>>(Q, K, idxk, S);
    k2_topk<<<BH, 256>>>();
    k3_attn<<<dim3(NSPLIT, BH), 256>>>(K, V, Q);
    k3c_combine<<<BH, 256>>>();
    k4_csum<<<dim3(NC, BH), 256>>>(V);
    k5_scan<<<dim3(NC/16, BH), 256>>>(V, out);
}